// round 5
// baseline (speedup 1.0000x reference)
#include <cuda_runtime.h>
#include <cuda_bf16.h>

#define N_V 4096
#define N_E 8192
#define HD  128
#define ATOM_DIM 64
#define BOND_DIM 32
#define N_LAYER 4

#define PB 148
#define PT 512
#define NWARP (PB * 16)

#define SCAN_CHUNK_F4 8192                     // 128 KB per scan chunk
#define PER_MAT_F4 (N_V * (N_E / 4))           // 8,388,608 float4 per matrix
#define NSCAN (2 * PER_MAT_F4 / SCAN_CHUNK_F4) // 2048
#define NLIN 192
#define NTASK (NLIN + NSCAN)                   // 2240

// ---------------------------------------------------------------------------
// Scratch
// ---------------------------------------------------------------------------
__device__ float g_he  [N_E * HD];
__device__ float g_hvA [N_V * HD];
__device__ float g_hvB [N_V * HD];
__device__ int   g_src [N_E];
__device__ int   g_dst [N_E];
__device__ unsigned g_count = 0;
__device__ volatile unsigned g_sense = 0;
__device__ unsigned g_task = 0;

// ---------------------------------------------------------------------------
// f32x2 packed helpers
// ---------------------------------------------------------------------------
__device__ __forceinline__ unsigned long long pack2(float a, float b) {
    unsigned long long r;
    asm("mov.b64 %0, {%1, %2};" : "=l"(r) : "f"(a), "f"(b));
    return r;
}
__device__ __forceinline__ void fma2(unsigned long long& d,
                                     unsigned long long a, unsigned long long b) {
    asm("fma.rn.f32x2 %0, %1, %2, %0;" : "+l"(d) : "l"(a), "l"(b));
}
__device__ __forceinline__ float2 unpack2(unsigned long long v) {
    float2 r;
    asm("mov.b64 {%0, %1}, %2;" : "=f"(r.x), "=f"(r.y) : "l"(v));
    return r;
}
__device__ __forceinline__ float lrelu(float v) { return v > 0.0f ? v : 0.01f * v; }

// ---------------------------------------------------------------------------
// Grid barrier: arrival = 1 atomic/block; wait = volatile load poll
// ---------------------------------------------------------------------------
__device__ __forceinline__ void gsync() {
    __syncthreads();
    if (threadIdx.x == 0) {
        __threadfence();
        unsigned gen = g_sense;
        if (atomicAdd(&g_count, 1u) == PB - 1u) {
            g_count = 0;
            __threadfence();
            g_sense = gen + 1u;
        } else {
            while (g_sense == gen) { __nanosleep(32); }
        }
    }
    __syncthreads();
}

// ---------------------------------------------------------------------------
// One-hot scan chunk: 8192 float4, 512 threads, 2 passes of 8 in-flight loads
// ---------------------------------------------------------------------------
__device__ __forceinline__ void proc_f4(float4 v, int p, int* __restrict__ outp)
{
    if (v.x != 0.0f || v.y != 0.0f || v.z != 0.0f || v.w != 0.0f) {
        int lin = p << 2;
        int row = lin >> 13;
        int col = lin & (N_E - 1);
        if (v.x != 0.0f) outp[col + 0] = row;
        if (v.y != 0.0f) outp[col + 1] = row;
        if (v.z != 0.0f) outp[col + 2] = row;
        if (v.w != 0.0f) outp[col + 3] = row;
    }
}

__device__ void scan_chunk(const float* __restrict__ vew1,
                           const float* __restrict__ vew2,
                           int* __restrict__ src, int* __restrict__ dst,
                           int c, int tid)
{
    int start = c * SCAN_CHUNK_F4;
    const float* mat; int* outp; int local;
    if (start < PER_MAT_F4) { mat = vew1; outp = src; local = start; }
    else                    { mat = vew2; outp = dst; local = start - PER_MAT_F4; }
    const float4* m4 = reinterpret_cast<const float4*>(mat);
#pragma unroll
    for (int pass = 0; pass < 2; pass++) {
        int base = local + pass * 4096 + tid;
        float4 v[8];
#pragma unroll
        for (int u = 0; u < 8; u++) v[u] = __ldcs(&m4[base + u * 512]);
#pragma unroll
        for (int u = 0; u < 8; u++) proc_f4(v[u], base + u * 512, outp);
    }
}

// ---------------------------------------------------------------------------
// Stage W[128,K] row-major -> sW[k*128 + n] (transposed), 512 threads
// ---------------------------------------------------------------------------
template<int K>
__device__ __forceinline__ void stage_w(const float* __restrict__ W, float* sW, int tid)
{
    int n  = tid & 127;
    int kq = (tid >> 7) * (K / 4);
#pragma unroll
    for (int j = 0; j < K / 16; j++) {
        float4 w = __ldg(reinterpret_cast<const float4*>(&W[n * K + kq + j * 4]));
        int k = kq + j * 4;
        sW[(k + 0) * 128 + n] = w.x;
        sW[(k + 1) * 128 + n] = w.y;
        sW[(k + 2) * 128 + n] = w.z;
        sW[(k + 3) * 128 + n] = w.w;
    }
}

// ---------------------------------------------------------------------------
// 512-thread GEMM accumulate: thread = 4 rows x 4 cols of C[64,128].
// sA row-major lda=K (smem), sW transposed [k][n]. f32x2 accumulators.
// ---------------------------------------------------------------------------
template<int K>
__device__ __forceinline__ void gemm512_acc(const float* __restrict__ sA,
                                            const float* __restrict__ sW,
                                            int row0, int c0,
                                            unsigned long long acc[4][2])
{
#pragma unroll
    for (int r = 0; r < 4; r++) { acc[r][0] = 0ull; acc[r][1] = 0ull; }
#pragma unroll 8
    for (int k0 = 0; k0 < K; k0 += 4) {
        float4 av[4];
#pragma unroll
        for (int r = 0; r < 4; r++)
            av[r] = *reinterpret_cast<const float4*>(&sA[(row0 + r) * K + k0]);
#pragma unroll
        for (int j = 0; j < 4; j++) {
            ulonglong2 ww = *reinterpret_cast<const ulonglong2*>(&sW[(k0 + j) * 128 + c0]);
#pragma unroll
            for (int r = 0; r < 4; r++) {
                float a = (j == 0) ? av[r].x : (j == 1) ? av[r].y
                        : (j == 2) ? av[r].z : av[r].w;
                unsigned long long aa = pack2(a, a);
                fma2(acc[r][0], aa, ww.x);
                fma2(acc[r][1], aa, ww.y);
            }
        }
    }
}

// ---------------------------------------------------------------------------
// Fused linear task: 64-row tile, stage1 (K1, leaky) -> smem, stage2 (128, tanh)
// -> global C (+ optional C2). Intermediate never touches global memory.
// ---------------------------------------------------------------------------
template<int K1>
__device__ void linear_task(const float* __restrict__ A0,
                            const float* __restrict__ W1, const float* __restrict__ b1,
                            const float* __restrict__ W2, const float* __restrict__ b2,
                            float* __restrict__ C, float* __restrict__ C2, int m0,
                            float* sW, float* sT, float* sA, int tid)
{
    const int ty   = tid >> 5;
    const int lane = tid & 31;
    const int c0   = lane * 4;
    const int row0 = ty * 4;

    // stage W1 (transposed) and A0 tile
    stage_w<K1>(W1, sW, tid);
    {
        const float4* A4 = reinterpret_cast<const float4*>(A0 + m0 * K1);
        float4* sA4 = reinterpret_cast<float4*>(sA);
#pragma unroll
        for (int idx = tid; idx < 64 * K1 / 4; idx += PT)
            sA4[idx] = __ldg(&A4[idx]);
    }
    __syncthreads();

    unsigned long long acc[4][2];
    gemm512_acc<K1>(sA, sW, row0, c0, acc);
    {
        float4 b4 = __ldg(reinterpret_cast<const float4*>(&b1[c0]));
#pragma unroll
        for (int r = 0; r < 4; r++) {
            float2 v0 = unpack2(acc[r][0]);
            float2 v1 = unpack2(acc[r][1]);
            float4 o = make_float4(lrelu(v0.x + b4.x), lrelu(v0.y + b4.y),
                                   lrelu(v1.x + b4.z), lrelu(v1.y + b4.w));
            *reinterpret_cast<float4*>(&sT[(row0 + r) * 128 + c0]) = o;
        }
    }
    __syncthreads();

    stage_w<128>(W2, sW, tid);
    __syncthreads();

    gemm512_acc<128>(sT, sW, row0, c0, acc);
    {
        float4 b4 = __ldg(reinterpret_cast<const float4*>(&b2[c0]));
#pragma unroll
        for (int r = 0; r < 4; r++) {
            float2 v0 = unpack2(acc[r][0]);
            float2 v1 = unpack2(acc[r][1]);
            float4 o = make_float4(tanhf(v0.x + b4.x), tanhf(v0.y + b4.y),
                                   tanhf(v1.x + b4.z), tanhf(v1.y + b4.w));
            int m = m0 + row0 + r;
            *reinterpret_cast<float4*>(&C[m * HD + c0]) = o;
            if (C2) *reinterpret_cast<float4*>(&C2[m * HD + c0]) = o;
        }
    }
    __syncthreads();
}

// ---------------------------------------------------------------------------
// The one kernel: phase1 (work-stolen scan chunks + fused linear tiles),
// grid barrier, 4 x (edge scatter | barrier | MLP | barrier), he_out.
// ---------------------------------------------------------------------------
__global__ __launch_bounds__(PT, 1)
void persist_kernel(const float* __restrict__ atom, const float* __restrict__ bond,
                    const float* __restrict__ vew1, const float* __restrict__ vew2,
                    const float* __restrict__ vW1, const float* __restrict__ vb1,
                    const float* __restrict__ vW2, const float* __restrict__ vb2,
                    const float* __restrict__ eW1, const float* __restrict__ eb1,
                    const float* __restrict__ eW2, const float* __restrict__ eb2,
                    const float* __restrict__ mlpW, const float* __restrict__ mlpb,
                    float* __restrict__ hvA, float* __restrict__ hvB,
                    float* __restrict__ he, int* __restrict__ src, int* __restrict__ dst,
                    float* __restrict__ hv_out, float* __restrict__ he_out)
{
    extern __shared__ float smem[];
    float* sW = smem;              // 16384 floats (64 KB)
    float* sT = smem + 16384;      //  8192 floats (32 KB)
    float* sA = smem + 24576;      //  4096 floats (16 KB)
    __shared__ int s_task;

    const int tid  = threadIdx.x;
    const int wid  = tid >> 5;
    const int lane = tid & 31;
    const int gw   = blockIdx.x * 16 + wid;

    // ---------------- phase 1: dynamic work (scans + fused linears) ----------
    while (true) {
        __syncthreads();
        if (tid == 0) s_task = atomicAdd(&g_task, 1u);
        __syncthreads();
        int t = s_task;
        if (t >= NTASK) break;

        // interleave: every 11th task is a linear tile (192 of them)
        int lin = t / 11;
        if ((t % 11 == 0) && lin < NLIN) {
            if (lin < 64)
                linear_task<ATOM_DIM>(atom, vW1, vb1, vW2, vb2,
                                      hvA, hvB, lin * 64, sW, sT, sA, tid);
            else
                linear_task<BOND_DIM>(bond, eW1, eb1, eW2, eb2,
                                      he, nullptr, (lin - 64) * 64, sW, sT, sA, tid);
        } else {
            int cnt = (t + 10) / 11; if (cnt > NLIN) cnt = NLIN;
            scan_chunk(vew1, vew2, src, dst, t - cnt, tid);
        }
    }
    gsync();
    if (blockIdx.x == 0 && tid == 0) g_task = 0;   // reset for next replay

    // ---------------- layers ------------------------------------------------
    const float4* he4 = reinterpret_cast<const float4*>(he);
    for (int l = 0; l < N_LAYER; l++) {
        // edge: hvB[src[e]] += relu(he[e] + hvA[dst[e]])
        for (int e = gw; e < N_E; e += NWARP) {
            int s = __ldg(&src[e]);
            int d = __ldg(&dst[e]);
            float4 a = __ldg(&he4[e * 32 + lane]);
            float4 g = __ldg(reinterpret_cast<const float4*>(hvA) + d * 32 + lane);
            float x = fmaxf(a.x + g.x, 0.0f);
            float y = fmaxf(a.y + g.y, 0.0f);
            float z = fmaxf(a.z + g.z, 0.0f);
            float w = fmaxf(a.w + g.w, 0.0f);
            float* p = &hvB[s * HD + lane * 4];
            asm volatile("red.global.add.v4.f32 [%0], {%1, %2, %3, %4};"
                         :: "l"(p), "f"(x), "f"(y), "f"(z), "f"(w) : "memory");
        }
        gsync();

        // MLP: hvA = leaky(hvB @ W_l^T + b); dual-store copy
        const float* Wl = mlpW + l * (HD * HD);
        const float* bl = mlpb + l * HD;
        float* C2 = (l == N_LAYER - 1) ? hv_out : hvB;

        stage_w<128>(Wl, sW, tid);
        __syncthreads();

        int g = blockIdx.x + PB * wid;          // warp task: 4 rows
        if (g < N_V / 4) {
            const int m0 = g * 4;
            const int c0 = lane * 4;
            unsigned long long acc[4][2];
#pragma unroll
            for (int r = 0; r < 4; r++) { acc[r][0] = 0ull; acc[r][1] = 0ull; }
#pragma unroll 8
            for (int k0 = 0; k0 < HD; k0 += 4) {
                float4 av[4];
#pragma unroll
                for (int r = 0; r < 4; r++)
                    av[r] = *reinterpret_cast<const float4*>(&hvB[(m0 + r) * HD + k0]);
#pragma unroll
                for (int j = 0; j < 4; j++) {
                    ulonglong2 ww = *reinterpret_cast<const ulonglong2*>(&sW[(k0 + j) * 128 + c0]);
#pragma unroll
                    for (int r = 0; r < 4; r++) {
                        float a = (j == 0) ? av[r].x : (j == 1) ? av[r].y
                                : (j == 2) ? av[r].z : av[r].w;
                        unsigned long long aa = pack2(a, a);
                        fma2(acc[r][0], aa, ww.x);
                        fma2(acc[r][1], aa, ww.y);
                    }
                }
            }
            float4 b4 = __ldg(reinterpret_cast<const float4*>(&bl[c0]));
#pragma unroll
            for (int r = 0; r < 4; r++) {
                float2 v0 = unpack2(acc[r][0]);
                float2 v1 = unpack2(acc[r][1]);
                float4 o = make_float4(lrelu(v0.x + b4.x), lrelu(v0.y + b4.y),
                                       lrelu(v1.x + b4.z), lrelu(v1.y + b4.w));
                int m = m0 + r;
                *reinterpret_cast<float4*>(&hvA[m * HD + c0]) = o;
                *reinterpret_cast<float4*>(&C2 [m * HD + c0]) = o;
            }
        }
        gsync();
    }

    // ---------------- he_out = [hv[src] | hv[dst] | he] ----------------------
    const float4* hv4 = reinterpret_cast<const float4*>(hvA);
    float4* out4 = reinterpret_cast<float4*>(he_out);
    for (int e = gw; e < N_E; e += NWARP) {
        int s = __ldg(&src[e]);
        int d = __ldg(&dst[e]);
        out4[e * 96 + lane]      = __ldg(&hv4[s * 32 + lane]);
        out4[e * 96 + 32 + lane] = __ldg(&hv4[d * 32 + lane]);
        out4[e * 96 + 64 + lane] = __ldg(&he4[e * 32 + lane]);
    }
}

// ---------------------------------------------------------------------------
// Launcher
// ---------------------------------------------------------------------------
extern "C" void kernel_launch(void* const* d_in, const int* in_sizes, int n_in,
                              void* d_out, int out_size)
{
    const float* atom = (const float*)d_in[0];
    const float* bond = (const float*)d_in[1];
    const float* vew1 = (const float*)d_in[2];
    const float* vew2 = (const float*)d_in[3];
    const float* vW1  = (const float*)d_in[4];
    const float* vb1  = (const float*)d_in[5];
    const float* vW2  = (const float*)d_in[6];
    const float* vb2  = (const float*)d_in[7];
    const float* eW1  = (const float*)d_in[8];
    const float* eb1  = (const float*)d_in[9];
    const float* eW2  = (const float*)d_in[10];
    const float* eb2  = (const float*)d_in[11];
    const float* mlpW = (const float*)d_in[12];
    const float* mlpb = (const float*)d_in[13];

    float *he, *hvA, *hvB;
    int *src, *dst;
    cudaGetSymbolAddress((void**)&he,  g_he);
    cudaGetSymbolAddress((void**)&hvA, g_hvA);
    cudaGetSymbolAddress((void**)&hvB, g_hvB);
    cudaGetSymbolAddress((void**)&src, g_src);
    cudaGetSymbolAddress((void**)&dst, g_dst);

    float* hv_out = (float*)d_out;
    float* he_out = (float*)d_out + (long long)N_V * HD;

    cudaFuncSetAttribute(persist_kernel,
                         cudaFuncAttributeMaxDynamicSharedMemorySize, 114688);

    persist_kernel<<<PB, PT, 114688>>>(atom, bond, vew1, vew2,
                                       vW1, vb1, vW2, vb2,
                                       eW1, eb1, eW2, eb2,
                                       mlpW, mlpb,
                                       hvA, hvB, he, src, dst,
                                       hv_out, he_out);
}